// round 8
// baseline (speedup 1.0000x reference)
#include <cuda_runtime.h>

#define DECAYF 0.951229424500714f   // exp(-1/20)

// Persistent state (no allocs allowed)
__device__ float g_vm0[2097152];      // [16 b][32 o][64][64]
__device__ float g_s0f[2097152];
__device__ float g_vm1[4194304];      // [16 b][64 o][64][64]
__device__ float g_flatT[1048576];    // pooled spikes [i=65536][b=16]
__device__ float g_part[524288];      // dense0 partials [is=64][b=16][j=512]
__device__ float g_vm2[8192];         // [b][j]
__device__ float g_vm3[176], g_acc[176];
__device__ float g_nop[32];

// ---- packed f32x2 helpers ----
__device__ __forceinline__ unsigned long long pack2(float a, float b) {
    unsigned long long r;
    asm("mov.b64 %0, {%1, %2};" : "=l"(r)
        : "r"(__float_as_uint(a)), "r"(__float_as_uint(b)));
    return r;
}
__device__ __forceinline__ void unpack2(unsigned long long v, float& a, float& b) {
    unsigned lo, hi;
    asm("mov.b64 {%0, %1}, %2;" : "=r"(lo), "=r"(hi) : "l"(v));
    a = __uint_as_float(lo); b = __uint_as_float(hi);
}
#define FMA2(acc, w, s) asm("fma.rn.f32x2 %0, %1, %2, %0;" : "+l"(acc) : "l"(w), "l"(s))
#define ADD2(acc, v)    asm("add.rn.f32x2 %0, %0, %1;"      : "+l"(acc) : "l"(v))

// dummy kernel: with two of these, ncu-captured launch (#3) = k_conv1(t=0)
__global__ void k_nop() { g_nop[threadIdx.x] = 0.f; }

// ---------------------------------------------------------------------------
// conv0 (2->32, 3x3 pad1) + LIF0.  grid = 16 b * 32 o = 512 blocks, 256 thr.
// ---------------------------------------------------------------------------
__global__ void __launch_bounds__(256) k_conv0(const float* __restrict__ in,
                                               const float* __restrict__ W0, int t)
{
    int bid = blockIdx.x;
    int o = bid & 31, b = bid >> 5;
    float w[18];
#pragma unroll
    for (int i = 0; i < 18; i++) w[i] = W0[o * 18 + i];
    const float* x0 = in + (((long)(b * 16 + t)) << 13);

#pragma unroll 4
    for (int p = threadIdx.x; p < 4096; p += 256) {
        int y = p >> 6, x = p & 63;
        float acc = 0.f;
#pragma unroll
        for (int c = 0; c < 2; c++)
#pragma unroll
            for (int ky = 0; ky < 3; ky++) {
                int yy = y + ky - 1;
                if ((unsigned)yy < 64u)
#pragma unroll
                    for (int kx = 0; kx < 3; kx++) {
                        int xx = x + kx - 1;
                        if ((unsigned)xx < 64u) {
                            float v = x0[(c << 12) + (yy << 6) + xx];
                            v = fminf(fmaxf(v, 0.f), 1.f);
                            acc = fmaf(w[c * 9 + ky * 3 + kx], v, acc);
                        }
                    }
            }
        long idx = (((long)bid) << 12) + p;
        float vm;
        if (t) {
            float vp = g_vm0[idx];
            vm = vp * (vp > 0.5f ? 0.f : DECAYF) + acc;
        } else vm = acc;
        g_vm0[idx] = vm;
        g_s0f[idx] = vm > 0.5f ? 1.f : 0.f;
    }
}

// ---------------------------------------------------------------------------
// conv1 (32->64, 3x3) + LIF1 + fused 2x2 maxpool (binary OR) -> g_flatT.
// grid = 16 b * 16 tiles(16x16) * 2 och-halves = 512 blocks, 256 threads.
// Thread: 4 och-pairs x 4 px = 16 f32x2 accumulators.
// ---------------------------------------------------------------------------
__global__ void __launch_bounds__(256, 2) k_conv1(const float* __restrict__ W1, int t)
{
    extern __shared__ unsigned char sh1[];
    unsigned long long* wsm = (unsigned long long*)sh1;   // [ck=288][pair=16]
    float* ssm = (float*)(sh1 + 36864);                   // [c=32][18][18]

    int bid  = blockIdx.x;
    int oh   = bid & 1;
    int tile = (bid >> 1) & 15;
    int b    = bid >> 5;
    int ty0  = (tile >> 2) << 4, tx0 = (tile & 3) << 4;
    int tid  = threadIdx.x;
    int pg   = tid >> 6;          // 0..3 : pair group (4 pairs = 8 och)
    int pxg  = tid & 63;
    int row  = pxg & 15;
    int px0  = (pxg >> 4) << 2;   // 0,4,8,12

    for (int idx = tid; idx < 4608; idx += 256) {
        int ck = idx >> 4, pr = idx & 15;
        const float* wb = W1 + (oh * 32 + 2 * pr) * 288 + ck;
        wsm[ck * 16 + pr] = pack2(wb[0], wb[288]);
    }
    for (int idx = tid; idx < 10368; idx += 256) {
        int c = idx / 324, r = idx - c * 324;
        int yy = r / 18, xx = r - yy * 18;
        int y = ty0 - 1 + yy, x = tx0 - 1 + xx;
        float v = 0.f;
        if ((unsigned)y < 64u && (unsigned)x < 64u)
            v = g_s0f[(((b << 5) + c) << 12) + (y << 6) + x];
        ssm[idx] = v;
    }
    __syncthreads();

    unsigned long long acc[16];
#pragma unroll
    for (int i = 0; i < 16; i++) acc[i] = 0ull;

    for (int c = 0; c < 32; ++c) {
#pragma unroll
        for (int ky = 0; ky < 3; ++ky) {
            const float* rp = ssm + c * 324 + (row + ky) * 18 + px0;
            unsigned long long s2[6];
#pragma unroll
            for (int u = 0; u < 6; ++u) {
                float s = rp[u];
                s2[u] = pack2(s, s);
            }
#pragma unroll
            for (int kx = 0; kx < 3; ++kx) {
                const ulonglong2* wp =
                    (const ulonglong2*)(wsm + (c * 9 + ky * 3 + kx) * 16 + (pg << 2));
                ulonglong2 wa = wp[0], wb = wp[1];
                unsigned long long wv[4] = {wa.x, wa.y, wb.x, wb.y};
#pragma unroll
                for (int g = 0; g < 4; ++g)
#pragma unroll
                    for (int px = 0; px < 4; ++px)
                        FMA2(acc[g * 4 + px], wv[g], s2[kx + px]);
            }
        }
    }

    int y = ty0 + row, x = tx0 + px0;
    unsigned pool = 0u;
#pragma unroll
    for (int g = 0; g < 4; ++g) {
        int o0 = oh * 32 + (pg << 3) + 2 * g;
        long ibase = (((long)((b << 6) + o0)) << 12) + (y << 6) + x;
#pragma unroll
        for (int px = 0; px < 4; ++px) {
            float I0, I1; unpack2(acc[g * 4 + px], I0, I1);
            long i0 = ibase + px, i1 = i0 + 4096;
            float va, vb;
            if (t) {
                float vp0 = g_vm1[i0], vp1 = g_vm1[i1];
                va = vp0 * (vp0 > 0.5f ? 0.f : DECAYF) + I0;
                vb = vp1 * (vp1 > 0.5f ? 0.f : DECAYF) + I1;
            } else { va = I0; vb = I1; }
            g_vm1[i0] = va; g_vm1[i1] = vb;
            unsigned sa = va > 0.5f ? 1u : 0u;
            unsigned sb = vb > 0.5f ? 1u : 0u;
            int xp = px >> 1;
            pool |= (sa << (4 * g + xp));
            pool |= (sb << (4 * g + 2 + xp));
        }
    }
    pool |= __shfl_xor_sync(0xffffffffu, pool, 1);
    if ((row & 1) == 0) {
        int py = y >> 1, pxb = x >> 1;
#pragma unroll
        for (int ol = 0; ol < 8; ++ol) {
            int o = oh * 32 + (pg << 3) + ol;
            int base = (o << 10) + (py << 5) + pxb;
#pragma unroll
            for (int xp = 0; xp < 2; ++xp)
                g_flatT[((base + xp) << 4) + b] =
                    (float)((pool >> (ol * 2 + xp)) & 1u);
        }
    }
}

// ---------------------------------------------------------------------------
// dense0 partials: out[b][j] = sum_i flat[b][i] * D0[j][i].
// grid = 8 j-tiles(64) x 64 i-splits(1024) = 512 blocks, 256 thr.
// NEW split: tid = jq(8)*32 + pg(2)*16 + ig(16); thread = 8 j x 4 batch-pairs.
// Per (n,k): 4 LDS.64 feed 32 FFMA2 (1:8) -> smem crossbar at ~50% of FMA.
// The two pg halves of a warp load identical D0 float4s (merged in coalescer).
// ---------------------------------------------------------------------------
__global__ void __launch_bounds__(256, 2) k_dense0(const float* __restrict__ D0)
{
    extern __shared__ float sh[];                        // 64 KB
    unsigned long long* sb2 = (unsigned long long*)sh;   // k-interleaved pairs
    int jt = blockIdx.x & 7;
    int is = blockIdx.x >> 3;
    int tid = threadIdx.x;
    int ig = tid & 15;
    int pg = (tid >> 4) & 1;
    int jq = tid >> 5;
    int j0 = (jt << 6) + (jq << 3);
    int pbase = pg << 2;

    {   // stage flat chunk: [1024 i][16 b] -> k-interleaved pair-major
        const uint2* src = (const uint2*)(g_flatT + ((long)is << 14));
        uint2* dst = (uint2*)sb2;
        for (int n = tid; n < 8192; n += 256) {
            int i = n >> 3, p = n & 7;
            dst[(p << 10) + ((i & 3) << 8) + (i >> 2)] = src[n];
        }
    }
    __syncthreads();

    unsigned long long acc[32];                 // [jr=8][p=4]
#pragma unroll
    for (int q = 0; q < 32; q++) acc[q] = 0ull;

    const float4* dbase4 = (const float4*)(D0 + ((long)j0 << 16) + (is << 10));
#pragma unroll 1
    for (int n = 0; n < 16; ++n) {
        int i4 = ig + (n << 4);                 // float4 column index
        float4 dv[8];
#pragma unroll
        for (int jr = 0; jr < 8; ++jr)
            dv[jr] = dbase4[jr * 16384 + i4];
#pragma unroll
        for (int k = 0; k < 4; ++k) {
            unsigned long long sv[4];
#pragma unroll
            for (int p = 0; p < 4; ++p)
                sv[p] = sb2[((pbase + p) << 10) + (k << 8) + i4];
#pragma unroll
            for (int jr = 0; jr < 8; ++jr) {
                float d = (k == 0) ? dv[jr].x : (k == 1) ? dv[jr].y
                        : (k == 2) ? dv[jr].z : dv[jr].w;
                unsigned long long dd = pack2(d, d);
#pragma unroll
                for (int p = 0; p < 4; ++p)
                    FMA2(acc[jr * 4 + p], dd, sv[p]);
            }
        }
    }
    // butterfly reduce across the 16 ig lanes (pg bit untouched: offsets <16)
#pragma unroll
    for (int off = 8; off; off >>= 1)
#pragma unroll
        for (int q = 0; q < 32; q++) {
            unsigned long long v = __shfl_xor_sync(0xffffffffu, acc[q], off);
            ADD2(acc[q], v);
        }
    if (ig == 0) {
        // g_part layout: [is][b][j]
#pragma unroll
        for (int jr = 0; jr < 8; ++jr) {
            int j = j0 + jr;
#pragma unroll
            for (int p = 0; p < 4; ++p) {
                float a0, a1; unpack2(acc[jr * 4 + p], a0, a1);
                int bpair = pbase + p;
                g_part[(is << 13) + ((2 * bpair)     << 9) + j] = a0;
                g_part[(is << 13) + ((2 * bpair + 1) << 9) + j] = a1;
            }
        }
    }
}

// ---------------------------------------------------------------------------
// fused tail: per-batch block. lif2 reduce (coalesced over j) + dense1 + LIF3.
// grid = 16 (batch), 512 threads.
// ---------------------------------------------------------------------------
__global__ void __launch_bounds__(512) k_tail2(const float* __restrict__ D1,
                                               float* __restrict__ out, int t)
{
    __shared__ float s2[512];
    int b = blockIdx.x;
    int tid = threadIdx.x;     // = j
    float I = 0.f;
#pragma unroll 8
    for (int is = 0; is < 64; is++)
        I += g_part[(is << 13) + (b << 9) + tid];
    int idx = (b << 9) + tid;
    float vm;
    if (t) {
        float vp = g_vm2[idx];
        vm = vp * (vp > 0.5f ? 0.f : DECAYF) + I;
    } else vm = I;
    g_vm2[idx] = vm;
    s2[tid] = vm > 0.5f ? 1.f : 0.f;
    __syncthreads();

    int w = tid >> 5, lane = tid & 31;
    if (w < 11) {
        float acc = 0.f;
#pragma unroll
        for (int u = 0; u < 16; u++)
            acc = fmaf(s2[lane + (u << 5)], D1[(w << 9) + lane + (u << 5)], acc);
#pragma unroll
        for (int off = 16; off; off >>= 1)
            acc += __shfl_xor_sync(0xffffffffu, acc, off);
        if (lane == 0) {
            int oidx = b * 11 + w;
            float vm3;
            if (t) {
                float vp = g_vm3[oidx];
                vm3 = vp * (vp > 0.5f ? 0.f : DECAYF) + acc;
            } else vm3 = acc;
            float sp = vm3 > 0.5f ? 1.f : 0.f;
            g_vm3[oidx] = vm3;
            float a = (t ? g_acc[oidx] : 0.f) + sp;
            g_acc[oidx] = a;
            if (t == 15) out[oidx] = a * 0.0625f;
        }
    }
}

// ---------------------------------------------------------------------------
extern "C" void kernel_launch(void* const* d_in, const int* in_sizes, int n_in,
                              void* d_out, int out_size)
{
    (void)in_sizes; (void)n_in; (void)out_size;
    const float* input = (const float*)d_in[0];
    const float* W0    = (const float*)d_in[1];
    const float* W1    = (const float*)d_in[2];
    const float* D0    = (const float*)d_in[3];
    const float* D1    = (const float*)d_in[4];
    float* out = (float*)d_out;

    cudaFuncSetAttribute(k_conv1,  cudaFuncAttributeMaxDynamicSharedMemorySize, 78336);
    cudaFuncSetAttribute(k_dense0, cudaFuncAttributeMaxDynamicSharedMemorySize, 65536);

    // two alignment no-ops: ncu-captured launch (#3, 0-based) = k_conv1(t=0)
    k_nop<<<1, 32>>>();
    k_nop<<<1, 32>>>();

    for (int t = 0; t < 16; t++) {
        k_conv0 <<<512, 256>>>(input, W0, t);
        k_conv1 <<<512, 256, 78336>>>(W1, t);
        k_dense0<<<512, 256, 65536>>>(D0);
        k_tail2 <<<16, 512>>>(D1, out, t);
    }
}